// round 5
// baseline (speedup 1.0000x reference)
#include <cuda_runtime.h>

#define BATCH  16
#define HH     128
#define WW     128
#define HIDDEN 16
#define KS     9
#define PAD    4
#define NBLK   50
#define NCH_MAX (NBLK + 1)   // 51 feature channels max (x + 50 outputs)

// Persistent feature stack: [channel][batch][h][w], channel 0 = x, channel 1+i = y_i
__device__ float g_feats[(size_t)NCH_MAX * BATCH * HH * WW];

// ---- packed f32x2 helpers (Blackwell: 2 fp32 FMAs per instruction) ----
__device__ __forceinline__ unsigned long long pack2(float lo, float hi) {
    unsigned long long r;
    asm("mov.b64 %0, {%1, %2};" : "=l"(r) : "f"(lo), "f"(hi));
    return r;
}
__device__ __forceinline__ void unpack2(unsigned long long v, float& lo, float& hi) {
    asm("mov.b64 {%0, %1}, %2;" : "=f"(lo), "=f"(hi) : "l"(v));
}
__device__ __forceinline__ unsigned long long ffma2(unsigned long long a,
                                                    unsigned long long b,
                                                    unsigned long long c) {
    unsigned long long d;
    asm("fma.rn.f32x2 %0, %1, %2, %3;" : "=l"(d) : "l"(a), "l"(b), "l"(c));
    return d;
}

// Tile: 32x32 output pixels per CTA, 256 threads (32 wide x 8), 4 rows per thread.
#define TW  32
#define TH  32
#define ITW (TW + 2 * PAD)   // 40
#define ITH (TH + 2 * PAD)   // 40

__global__ __launch_bounds__(256, 1) void dense_block_kernel(
    const float* __restrict__ w1,   // [NBLK][HIDDEN][NCH_MAX][9][9]
    const float* __restrict__ b1,   // [NBLK][HIDDEN]
    const float* __restrict__ w2,   // [NBLK][HIDDEN]
    const float* __restrict__ b2,   // [NBLK]
    float* __restrict__ out,        // [BATCH][NBLK][HH][WW]
    int blk)
{
    __shared__ __align__(16) float s_in[ITH * ITW];        // 40*40 = 1600 floats
    __shared__ __align__(16) float s_w[KS * KS * HIDDEN];  // [tap][oc], 81*16

    const int tx     = threadIdx.x & 31;
    const int ty     = threadIdx.x >> 5;        // 0..7
    const int tile_x = blockIdx.x * TW;
    const int tile_y = blockIdx.y * TH;
    const int b      = blockIdx.z;
    const int nch    = blk + 1;

    // Accumulators: 4 pixel-rows x 8 oc-pairs, packed f32x2
    unsigned long long acc[4][8];
    #pragma unroll
    for (int r = 0; r < 4; ++r)
        #pragma unroll
        for (int p = 0; p < 8; ++p) acc[r][p] = 0ull;

    const float* w1blk = w1 + (size_t)blk * HIDDEN * NCH_MAX * (KS * KS);

    for (int c = 0; c < nch; ++c) {
        __syncthreads();  // protect smem from previous iteration's readers

        // Cooperative load of 40x40 halo tile for input channel c (zero-padded)
        const float* fch = g_feats + ((size_t)c * BATCH + b) * (HH * WW);
        for (int idx = threadIdx.x; idx < ITH * ITW; idx += 256) {
            int r  = idx / ITW;
            int cc = idx - r * ITW;
            int gy = tile_y + r - PAD;
            int gx = tile_x + cc - PAD;
            float v = 0.0f;
            if ((unsigned)gy < (unsigned)HH && (unsigned)gx < (unsigned)WW)
                v = fch[gy * WW + gx];
            s_in[idx] = v;
        }
        // Repack weights: s_w[tap*16 + oc] = w1[blk][oc][c][tap]
        const float* wc = w1blk + (size_t)c * (KS * KS);
        for (int idx = threadIdx.x; idx < HIDDEN * KS * KS; idx += 256) {
            int oc  = idx / (KS * KS);
            int tap = idx - oc * (KS * KS);
            s_w[tap * HIDDEN + oc] = wc[(size_t)oc * (NCH_MAX * KS * KS) + tap];
        }
        __syncthreads();

        #pragma unroll 1   // keep loop body inside I$ (body ~7KB when kw unrolled)
        for (int kh = 0; kh < KS; ++kh) {
            const float* r0 = s_in + (ty + kh) * ITW + tx;
            #pragma unroll
            for (int kw = 0; kw < KS; ++kw) {
                // 8 broadcast LDS.64: weights for oc-pairs at this tap
                const unsigned long long* wp =
                    (const unsigned long long*)(s_w + (kh * KS + kw) * HIDDEN);
                unsigned long long wr[8];
                #pragma unroll
                for (int p = 0; p < 8; ++p) wr[p] = wp[p];
                #pragma unroll
                for (int r = 0; r < 4; ++r) {
                    float v = r0[r * 8 * ITW + kw];
                    unsigned long long vp = pack2(v, v);
                    #pragma unroll
                    for (int p = 0; p < 8; ++p)
                        acc[r][p] = ffma2(vp, wr[p], acc[r][p]);
                }
            }
        }
    }

    // Epilogue: bias + ReLU + 1x1 projection + sigmoid, write out + new feat channel
    float b1r[HIDDEN], w2r[HIDDEN];
    #pragma unroll
    for (int oc = 0; oc < HIDDEN; ++oc) {
        b1r[oc] = __ldg(&b1[blk * HIDDEN + oc]);
        w2r[oc] = __ldg(&w2[blk * HIDDEN + oc]);
    }
    const float b2v = __ldg(&b2[blk]);

    #pragma unroll
    for (int r = 0; r < 4; ++r) {
        float s = b2v;
        #pragma unroll
        for (int p = 0; p < 8; ++p) {
            float a, bb;
            unpack2(acc[r][p], a, bb);
            s += fmaxf(a + b1r[2 * p], 0.0f) * w2r[2 * p];
            s += fmaxf(bb + b1r[2 * p + 1], 0.0f) * w2r[2 * p + 1];
        }
        float y = 1.0f / (1.0f + __expf(-s));
        int h = tile_y + ty + 8 * r;
        int w = tile_x + tx;
        out[(((size_t)b * NBLK + blk) * HH + h) * WW + w] = y;
        g_feats[(((size_t)(blk + 1) * BATCH + b) * HH + h) * WW + w] = y;
    }
}

__global__ void copy_x_kernel(const float* __restrict__ x) {
    int i = blockIdx.x * blockDim.x + threadIdx.x;
    g_feats[i] = x[i];   // channel 0 layout [b][h][w] matches x (B,1,H,W)
}

extern "C" void kernel_launch(void* const* d_in, const int* in_sizes, int n_in,
                              void* d_out, int out_size) {
    const float* x  = (const float*)d_in[0];
    const float* w1 = (const float*)d_in[1];
    const float* b1 = (const float*)d_in[2];
    const float* w2 = (const float*)d_in[3];
    const float* b2 = (const float*)d_in[4];
    float* out = (float*)d_out;

    copy_x_kernel<<<(BATCH * HH * WW) / 256, 256>>>(x);

    dim3 grid(WW / TW, HH / TH, BATCH);  // 4 x 4 x 16 = 256 CTAs
    for (int i = 0; i < NBLK; ++i)
        dense_block_kernel<<<grid, 256>>>(w1, b1, w2, b2, out, i);
}

// round 9
// speedup vs baseline: 1.0425x; 1.0425x over previous
#include <cuda_runtime.h>
#include <cuda_bf16.h>
#include <stdint.h>

#define BATCH 16
#define HH    128
#define WW    128
#define HID   16
#define KS    9
#define NBLK  50
#define CH_PAD 64
#define HP    136            // 128 + 4 halo each side
#define G     8              // output rows per CTA (1 per warp)
#define MAXCK 4

#define A_HL_BYTES (16 * HP * 32)        // 16 rows x 136 slots x 32B = 69632
#define SM_A_BYTES (2 * A_HL_BYTES)      // hi + lo = 139264
#define SM_B_BYTES (81 * 1024)           // 81 taps x [hl2][c16][oc16] bf16 = 82944
#define SM_TOTAL   (SM_A_BYTES + SM_B_BYTES)   // 222208

// features, channel-interleaved: idx ((b*HP+h)*HP+x)*CH_PAD + c ; halo stays 0
__device__ __align__(16) __nv_bfloat16 g_hi[(size_t)BATCH * HP * HP * CH_PAD];
__device__ __align__(16) __nv_bfloat16 g_lo[(size_t)BATCH * HP * HP * CH_PAD];
// weights per (blk,ck): [tap81][hl2][c16][oc16] bf16, 512 elems/tap
__device__ __align__(16) __nv_bfloat16 g_wb[(size_t)NBLK * MAXCK * 81 * 512];

__device__ __forceinline__ uint32_t sptr(const void* p) {
    return (uint32_t)__cvta_generic_to_shared(p);
}
__device__ __forceinline__ void ldsm4(uint32_t* r, uint32_t a) {
    asm volatile("ldmatrix.sync.aligned.m8n8.x4.shared.b16 {%0,%1,%2,%3}, [%4];"
        : "=r"(r[0]), "=r"(r[1]), "=r"(r[2]), "=r"(r[3]) : "r"(a));
}
__device__ __forceinline__ void ldsm4t(uint32_t* r, uint32_t a) {
    asm volatile("ldmatrix.sync.aligned.m8n8.x4.trans.shared.b16 {%0,%1,%2,%3}, [%4];"
        : "=r"(r[0]), "=r"(r[1]), "=r"(r[2]), "=r"(r[3]) : "r"(a));
}
__device__ __forceinline__ void mma16816(float* c, const uint32_t* a,
                                         uint32_t b0, uint32_t b1) {
    asm volatile(
        "mma.sync.aligned.m16n8k16.row.col.f32.bf16.bf16.f32 "
        "{%0,%1,%2,%3},{%4,%5,%6,%7},{%8,%9},{%0,%1,%2,%3};"
        : "+f"(c[0]), "+f"(c[1]), "+f"(c[2]), "+f"(c[3])
        : "r"(a[0]), "r"(a[1]), "r"(a[2]), "r"(a[3]), "r"(b0), "r"(b1));
}

// ---- prep: split weights into bf16 hi/lo, layout [tap][hl][c16][oc16] ----
__global__ void prep_w_kernel(const float* __restrict__ w1) {
    int bi  = blockIdx.x;                 // NBLK*MAXCK*81
    int tap = bi % 81;
    int ck  = (bi / 81) & 3;
    int blk = bi / (81 * 4);
    int oc  = threadIdx.x & 15;
    int c   = threadIdx.x >> 4;
    int cg  = ck * 16 + c;
    float w = 0.f;
    if (cg < blk + 1)
        w = w1[(((size_t)blk * HID + oc) * (NBLK + 1) + cg) * 81 + tap];
    __nv_bfloat16 hi = __float2bfloat16(w);
    __nv_bfloat16 lo = __float2bfloat16(w - __bfloat162float(hi));
    size_t base = ((size_t)(blk * MAXCK + ck) * 81 + tap) * 512;
    g_wb[base +       c * 16 + oc] = hi;
    g_wb[base + 256 + c * 16 + oc] = lo;
}

__global__ void copy_x_kernel(const float* __restrict__ x) {
    int t = blockIdx.x * blockDim.x + threadIdx.x;   // b*H*W
    int w = t & (WW - 1), h = (t >> 7) & (HH - 1), b = t >> 14;
    float v = x[t];
    __nv_bfloat16 hi = __float2bfloat16(v);
    __nv_bfloat16 lo = __float2bfloat16(v - __bfloat162float(hi));
    size_t gi = (((size_t)b * HP + h + 4) * HP + w + 4) * CH_PAD;
    g_hi[gi] = hi; g_lo[gi] = lo;
}

__global__ void __launch_bounds__(256, 1) dense_block_mma(
    const float* __restrict__ b1, const float* __restrict__ w2,
    const float* __restrict__ b2, float* __restrict__ out, int blk)
{
    extern __shared__ __align__(128) char smem[];
    const int tid  = threadIdx.x;
    const int wid  = tid >> 5;           // 0..7 -> output row
    const int lane = tid & 31;
    const int gid  = lane >> 2;          // 0..7
    const int tig  = lane & 3;           // 0..3
    const int r0   = blockIdx.x * G;     // output row base
    const int bb   = blockIdx.y;

    const uint32_t sA = sptr(smem);
    const uint32_t sB = sA + SM_A_BYTES;
    // shared ldmatrix lane offset (rows stride 32B, col-half +16B)
    const uint32_t laneoff = (uint32_t)((lane & 15) * 32 + (lane >> 4) * 16);

    float acc[G][2][4];
    #pragma unroll
    for (int t = 0; t < G; ++t)
        #pragma unroll
        for (int nh = 0; nh < 2; ++nh)
            #pragma unroll
            for (int q = 0; q < 4; ++q) acc[t][nh][q] = 0.f;

    const int nchunks = (blk + 16) >> 4;

    for (int ck = 0; ck < nchunks; ++ck) {
        __syncthreads();   // previous chunk's readers done

        // B: straight 82944B copy
        {
            const float4* src = (const float4*)(g_wb + ((size_t)blk * MAXCK + ck) * 81 * 512);
            float4* dst = (float4*)(smem + SM_A_BYTES);
            for (int i = tid; i < SM_B_BYTES / 16; i += 256) dst[i] = src[i];
        }
        // A: 16 rows x 136 slots, hi plane then lo plane
        {
            const int c0 = ck * 16;
            float4* pa = (float4*)smem;
            for (int s = tid; s < 16 * HP; s += 256) {
                int lr = s / HP, xs = s - lr * HP;
                size_t gi = (((size_t)bb * HP + r0 + lr) * HP + xs) * CH_PAD + c0;
                int d = s * 2;
                pa[d]            = *(const float4*)(g_hi + gi);
                pa[d + 1]        = *(const float4*)(g_hi + gi + 8);
                pa[4352 + d]     = *(const float4*)(g_lo + gi);
                pa[4352 + d + 1] = *(const float4*)(g_lo + gi + 8);
            }
        }
        __syncthreads();

        #pragma unroll 1
        for (int kh = 0; kh < KS; ++kh) {
            const uint32_t aRowHi = sA + (wid + kh) * 4352 + laneoff;
            const uint32_t aRowLo = aRowHi + A_HL_BYTES;
            #pragma unroll 1
            for (int kw = 0; kw < KS; ++kw) {
                const uint32_t bTap = sB + (kh * KS + kw) * 1024 + laneoff;
                uint32_t bh[4], bl[4];
                ldsm4t(bh, bTap);        // [c16][oc16] hi -> B frags n0-7, n8-15
                ldsm4t(bl, bTap + 512);
                #pragma unroll
                for (int t = 0; t < G; ++t) {
                    const uint32_t aoff = (uint32_t)((16 * t + kw) * 32);
                    uint32_t ahi[4], alo[4];
                    ldsm4(ahi, aRowHi + aoff);
                    mma16816(acc[t][0], ahi, bh[0], bh[1]);
                    mma16816(acc[t][1], ahi, bh[2], bh[3]);
                    mma16816(acc[t][0], ahi, bl[0], bl[1]);
                    mma16816(acc[t][1], ahi, bl[2], bl[3]);
                    ldsm4(alo, aRowLo + aoff);
                    mma16816(acc[t][0], alo, bh[0], bh[1]);
                    mma16816(acc[t][1], alo, bh[2], bh[3]);
                }
            }
        }
    }

    // ---- epilogue ----
    // thread's 4 output channels: o0=2*tig, o0+1, o0+8, o0+9
    const int o0 = 2 * tig;
    const float b1a = __ldg(&b1[blk * HID + o0]);
    const float b1b = __ldg(&b1[blk * HID + o0 + 1]);
    const float b1c = __ldg(&b1[blk * HID + o0 + 8]);
    const float b1d = __ldg(&b1[blk * HID + o0 + 9]);
    const float w2a = __ldg(&w2[blk * HID + o0]);
    const float w2b = __ldg(&w2[blk * HID + o0 + 1]);
    const float w2c = __ldg(&w2[blk * HID + o0 + 8]);
    const float w2d = __ldg(&w2[blk * HID + o0 + 9]);
    const float b2v = __ldg(&b2[blk]);
    const int h = r0 + wid;

    #pragma unroll
    for (int t = 0; t < G; ++t) {
        #pragma unroll
        for (int half = 0; half < 2; ++half) {   // half 0: c0/c1 (pix gid), 1: c2/c3 (gid+8)
            float sA_ = fmaxf(acc[t][0][2 * half]     + b1a, 0.f) * w2a
                      + fmaxf(acc[t][0][2 * half + 1] + b1b, 0.f) * w2b
                      + fmaxf(acc[t][1][2 * half]     + b1c, 0.f) * w2c
                      + fmaxf(acc[t][1][2 * half + 1] + b1d, 0.f) * w2d;
            sA_ += __shfl_xor_sync(0xffffffffu, sA_, 1);
            sA_ += __shfl_xor_sync(0xffffffffu, sA_, 2);
            if (tig == 0) {
                const int px = 16 * t + gid + 8 * half;
                const float y = 1.0f / (1.0f + __expf(-(sA_ + b2v)));
                out[(((size_t)bb * NBLK + blk) * HH + h) * WW + px] = y;
                __nv_bfloat16 hi = __float2bfloat16(y);
                __nv_bfloat16 lo = __float2bfloat16(y - __bfloat162float(hi));
                size_t gi = (((size_t)bb * HP + h + 4) * HP + px + 4) * CH_PAD + blk + 1;
                g_hi[gi] = hi; g_lo[gi] = lo;
            }
        }
    }
}

extern "C" void kernel_launch(void* const* d_in, const int* in_sizes, int n_in,
                              void* d_out, int out_size) {
    const float* x  = (const float*)d_in[0];
    const float* w1 = (const float*)d_in[1];
    const float* b1 = (const float*)d_in[2];
    const float* w2 = (const float*)d_in[3];
    const float* b2 = (const float*)d_in[4];
    float* out = (float*)d_out;

    cudaFuncSetAttribute(dense_block_mma,
                         cudaFuncAttributeMaxDynamicSharedMemorySize, SM_TOTAL);

    prep_w_kernel<<<NBLK * MAXCK * 81, 256>>>(w1);          // 16200 blocks
    copy_x_kernel<<<(BATCH * HH * WW) / 256, 256>>>(x);

    dim3 grid(HH / G, BATCH);                               // 16 x 16 = 256 CTAs
    for (int i = 0; i < NBLK; ++i)
        dense_block_mma<<<grid, 256, SM_TOTAL>>>(b1, w2, b2, out, i);
}

// round 10
// speedup vs baseline: 1.5035x; 1.4422x over previous
#include <cuda_runtime.h>
#include <cuda_bf16.h>
#include <stdint.h>

#define BATCH 16
#define HH    128
#define WW    128
#define HID   16
#define KS    9
#define NBLK  50
#define CH_PAD 64
#define HP    136            // 128 + 4 halo each side
#define G     8              // output rows per CTA (2 warps per row)
#define MAXCK 4
#define NT    512            // threads per CTA (16 warps)

#define A_HL_BYTES (16 * HP * 32)        // 16 rows x 136 slots x 32B = 69632
#define SM_A_BYTES (2 * A_HL_BYTES)      // hi + lo = 139264
#define SM_B_BYTES (81 * 1024)           // 81 taps x [hl2][c16][oc16] bf16 = 82944
#define SM_TOTAL   (SM_A_BYTES + SM_B_BYTES)   // 222208

// features, channel-interleaved: idx ((b*HP+h)*HP+x)*CH_PAD + c ; halo stays 0
__device__ __align__(16) __nv_bfloat16 g_hi[(size_t)BATCH * HP * HP * CH_PAD];
__device__ __align__(16) __nv_bfloat16 g_lo[(size_t)BATCH * HP * HP * CH_PAD];
// weights per (blk,ck): [tap81][hl2][c16][oc16] bf16, 512 elems/tap
__device__ __align__(16) __nv_bfloat16 g_wb[(size_t)NBLK * MAXCK * 81 * 512];

__device__ __forceinline__ uint32_t sptr(const void* p) {
    return (uint32_t)__cvta_generic_to_shared(p);
}
__device__ __forceinline__ void ldsm4(uint32_t* r, uint32_t a) {
    asm volatile("ldmatrix.sync.aligned.m8n8.x4.shared.b16 {%0,%1,%2,%3}, [%4];"
        : "=r"(r[0]), "=r"(r[1]), "=r"(r[2]), "=r"(r[3]) : "r"(a));
}
__device__ __forceinline__ void ldsm4t(uint32_t* r, uint32_t a) {
    asm volatile("ldmatrix.sync.aligned.m8n8.x4.trans.shared.b16 {%0,%1,%2,%3}, [%4];"
        : "=r"(r[0]), "=r"(r[1]), "=r"(r[2]), "=r"(r[3]) : "r"(a));
}
__device__ __forceinline__ void mma16816(float* c, const uint32_t* a,
                                         uint32_t b0, uint32_t b1) {
    asm volatile(
        "mma.sync.aligned.m16n8k16.row.col.f32.bf16.bf16.f32 "
        "{%0,%1,%2,%3},{%4,%5,%6,%7},{%8,%9},{%0,%1,%2,%3};"
        : "+f"(c[0]), "+f"(c[1]), "+f"(c[2]), "+f"(c[3])
        : "r"(a[0]), "r"(a[1]), "r"(a[2]), "r"(a[3]), "r"(b0), "r"(b1));
}

// ---- prep: split weights into bf16 hi/lo, layout [tap][hl][c16][oc16] ----
__global__ void prep_w_kernel(const float* __restrict__ w1) {
    int bi  = blockIdx.x;                 // NBLK*MAXCK*81
    int tap = bi % 81;
    int ck  = (bi / 81) & 3;
    int blk = bi / (81 * 4);
    int oc  = threadIdx.x & 15;
    int c   = threadIdx.x >> 4;
    int cg  = ck * 16 + c;
    float w = 0.f;
    if (cg < blk + 1)
        w = w1[(((size_t)blk * HID + oc) * (NBLK + 1) + cg) * 81 + tap];
    __nv_bfloat16 hi = __float2bfloat16(w);
    __nv_bfloat16 lo = __float2bfloat16(w - __bfloat162float(hi));
    size_t base = ((size_t)(blk * MAXCK + ck) * 81 + tap) * 512;
    g_wb[base +       c * 16 + oc] = hi;
    g_wb[base + 256 + c * 16 + oc] = lo;
}

__global__ void copy_x_kernel(const float* __restrict__ x) {
    int t = blockIdx.x * blockDim.x + threadIdx.x;   // b*H*W
    int w = t & (WW - 1), h = (t >> 7) & (HH - 1), b = t >> 14;
    float v = x[t];
    __nv_bfloat16 hi = __float2bfloat16(v);
    __nv_bfloat16 lo = __float2bfloat16(v - __bfloat162float(hi));
    size_t gi = (((size_t)b * HP + h + 4) * HP + w + 4) * CH_PAD;
    g_hi[gi] = hi; g_lo[gi] = lo;
}

__global__ void __launch_bounds__(NT, 1) dense_block_mma(
    const float* __restrict__ b1, const float* __restrict__ w2,
    const float* __restrict__ b2, float* __restrict__ out, int blk)
{
    extern __shared__ __align__(128) char smem[];
    const int tid  = threadIdx.x;
    const int wid  = tid >> 5;           // 0..15
    const int lane = tid & 31;
    const int row  = wid >> 1;           // output row within CTA (0..7)
    const int half = wid & 1;            // pixel half: 0 -> px 0-63, 1 -> 64-127
    const int gid  = lane >> 2;          // 0..7
    const int tig  = lane & 3;           // 0..3
    const int r0   = blockIdx.x * G;     // output row base
    const int bb   = blockIdx.y;

    const uint32_t sA = sptr(smem);
    const uint32_t sB = sA + SM_A_BYTES;
    const uint32_t laneoff = (uint32_t)((lane & 15) * 32 + (lane >> 4) * 16);

    float acc[4][2][4];   // 4 m-tiles x 2 oc-halves x 4
    #pragma unroll
    for (int t = 0; t < 4; ++t)
        #pragma unroll
        for (int nh = 0; nh < 2; ++nh)
            #pragma unroll
            for (int q = 0; q < 4; ++q) acc[t][nh][q] = 0.f;

    const int nchunks = (blk + 16) >> 4;

    for (int ck = 0; ck < nchunks; ++ck) {
        __syncthreads();   // previous chunk's readers done

        // B: straight 82944B copy
        {
            const float4* src = (const float4*)(g_wb + ((size_t)blk * MAXCK + ck) * 81 * 512);
            float4* dst = (float4*)(smem + SM_A_BYTES);
            for (int i = tid; i < SM_B_BYTES / 16; i += NT) dst[i] = src[i];
        }
        // A: 16 rows x 136 slots, hi plane then lo plane
        {
            const int c0 = ck * 16;
            float4* pa = (float4*)smem;
            for (int s = tid; s < 16 * HP; s += NT) {
                int lr = s / HP, xs = s - lr * HP;
                size_t gi = (((size_t)bb * HP + r0 + lr) * HP + xs) * CH_PAD + c0;
                int d = s * 2;
                pa[d]            = *(const float4*)(g_hi + gi);
                pa[d + 1]        = *(const float4*)(g_hi + gi + 8);
                pa[4352 + d]     = *(const float4*)(g_lo + gi);
                pa[4352 + d + 1] = *(const float4*)(g_lo + gi + 8);
            }
        }
        __syncthreads();

        #pragma unroll 1
        for (int kh = 0; kh < KS; ++kh) {
            const uint32_t aRowHi = sA + (row + kh) * 4352 + laneoff;
            const uint32_t aRowLo = aRowHi + A_HL_BYTES;
            #pragma unroll 1
            for (int kw = 0; kw < KS; ++kw) {
                const uint32_t bTap = sB + (kh * KS + kw) * 1024 + laneoff;
                uint32_t bh[4], bl[4];
                ldsm4t(bh, bTap);        // [c16][oc16] hi
                ldsm4t(bl, bTap + 512);  // lo
                #pragma unroll
                for (int t = 0; t < 4; ++t) {
                    const uint32_t aoff = (uint32_t)((64 * half + 16 * t + kw) * 32);
                    uint32_t ahi[4], alo[4];
                    ldsm4(ahi, aRowHi + aoff);
                    mma16816(acc[t][0], ahi, bh[0], bh[1]);
                    mma16816(acc[t][1], ahi, bh[2], bh[3]);
                    mma16816(acc[t][0], ahi, bl[0], bl[1]);
                    mma16816(acc[t][1], ahi, bl[2], bl[3]);
                    ldsm4(alo, aRowLo + aoff);
                    mma16816(acc[t][0], alo, bh[0], bh[1]);
                    mma16816(acc[t][1], alo, bh[2], bh[3]);
                }
            }
        }
    }

    // ---- epilogue ----
    // thread's 4 output channels: o0=2*tig, o0+1, o0+8, o0+9
    const int o0 = 2 * tig;
    const float b1a = __ldg(&b1[blk * HID + o0]);
    const float b1b = __ldg(&b1[blk * HID + o0 + 1]);
    const float b1c = __ldg(&b1[blk * HID + o0 + 8]);
    const float b1d = __ldg(&b1[blk * HID + o0 + 9]);
    const float w2a = __ldg(&w2[blk * HID + o0]);
    const float w2b = __ldg(&w2[blk * HID + o0 + 1]);
    const float w2c = __ldg(&w2[blk * HID + o0 + 8]);
    const float w2d = __ldg(&w2[blk * HID + o0 + 9]);
    const float b2v = __ldg(&b2[blk]);
    const int h = r0 + row;

    #pragma unroll
    for (int t = 0; t < 4; ++t) {
        #pragma unroll
        for (int mh = 0; mh < 2; ++mh) {  // mh 0: pixel gid (c0,c1), 1: gid+8 (c2,c3)
            float s = fmaxf(acc[t][0][2 * mh]     + b1a, 0.f) * w2a
                    + fmaxf(acc[t][0][2 * mh + 1] + b1b, 0.f) * w2b
                    + fmaxf(acc[t][1][2 * mh]     + b1c, 0.f) * w2c
                    + fmaxf(acc[t][1][2 * mh + 1] + b1d, 0.f) * w2d;
            s += __shfl_xor_sync(0xffffffffu, s, 1);
            s += __shfl_xor_sync(0xffffffffu, s, 2);
            if (tig == 0) {
                const int px = 64 * half + 16 * t + gid + 8 * mh;
                const float y = 1.0f / (1.0f + __expf(-(s + b2v)));
                out[(((size_t)bb * NBLK + blk) * HH + h) * WW + px] = y;
                __nv_bfloat16 hi = __float2bfloat16(y);
                __nv_bfloat16 lo = __float2bfloat16(y - __bfloat162float(hi));
                size_t gi = (((size_t)bb * HP + h + 4) * HP + px + 4) * CH_PAD + blk + 1;
                g_hi[gi] = hi; g_lo[gi] = lo;
            }
        }
    }
}

extern "C" void kernel_launch(void* const* d_in, const int* in_sizes, int n_in,
                              void* d_out, int out_size) {
    const float* x  = (const float*)d_in[0];
    const float* w1 = (const float*)d_in[1];
    const float* b1 = (const float*)d_in[2];
    const float* w2 = (const float*)d_in[3];
    const float* b2 = (const float*)d_in[4];
    float* out = (float*)d_out;

    cudaFuncSetAttribute(dense_block_mma,
                         cudaFuncAttributeMaxDynamicSharedMemorySize, SM_TOTAL);

    prep_w_kernel<<<NBLK * MAXCK * 81, 256>>>(w1);          // 16200 blocks
    copy_x_kernel<<<(BATCH * HH * WW) / 256, 256>>>(x);

    dim3 grid(HH / G, BATCH);                               // 16 x 16 = 256 CTAs
    for (int i = 0; i < NBLK; ++i)
        dense_block_mma<<<grid, NT, SM_TOTAL>>>(b1, w2, b2, out, i);
}